// round 3
// baseline (speedup 1.0000x reference)
#include <cuda_runtime.h>
#include <cstdint>
#include <cstdio>

// ---------------- problem constants ----------------
constexpr int NN  = 50000;   // nodes
constexpr int NE  = 800000;  // edges
constexpr int DD  = 128;     // channels
constexpr int NH  = 8;       // heads
constexpr int EDD = 32;      // edge_dim
constexpr int HD  = 512;     // mlp hidden
constexpr int GG  = 64;      // graphs
constexpr float NEG  = 0.2f;
constexpr float EPSC = 1e-5f;

#define NEG_INF (__int_as_float(0xff800000u))

// ---------------- device scratch (no allocs allowed) ----------------
__device__ float g_xl  [NN * DD];
__device__ float g_xr  [NN * DD];
__device__ float g_xres[NN * DD];
__device__ float g_xtmp[NN * DD];
__device__ float g_x2  [NN * DD];
__device__ float g_xcur[NN * DD];
__device__ float g_e   [(size_t)NE * DD];   // 409 MB
__device__ float g_h   [(size_t)NN * HD];   // 102 MB
__device__ float g_alpha[(size_t)NE * NH];

__device__ int g_deg   [NN];
__device__ int g_rowptr[NN + 1];
__device__ int g_wp    [NN];
__device__ int g_eids  [NE];
__device__ int g_gcnt  [GG];

__device__ float g_bnstat[2 * HD];
__device__ float g_bns[HD];
__device__ float g_bnt[HD];
__device__ float g_gstat[2 * GG];
__device__ float g_gmean[GG];
__device__ float g_ginv [GG];

// ---------------- setup kernels ----------------
__global__ void zero_init_kernel() {
    int i = blockIdx.x * blockDim.x + threadIdx.x;
    if (i < NN) g_deg[i] = 0;
    if (i < GG) g_gcnt[i] = 0;
}

__global__ void hist_kernel(const int* __restrict__ ei, const int* __restrict__ nb) {
    int i = blockIdx.x * blockDim.x + threadIdx.x;
    if (i < NE) atomicAdd(&g_deg[ei[NE + i]], 1);   // dst
    if (i < NN) atomicAdd(&g_gcnt[nb[i]], 1);
}

__global__ void scan_kernel() {
    __shared__ int part[1024];
    constexpr int CHUNK = (NN + 1023) / 1024;  // 49
    int t = threadIdx.x;
    int base = t * CHUNK;
    int s = 0;
    for (int i = 0; i < CHUNK; i++) {
        int idx = base + i;
        if (idx < NN) s += g_deg[idx];
    }
    part[t] = s;
    __syncthreads();
    for (int off = 1; off < 1024; off <<= 1) {
        int v = (t >= off) ? part[t - off] : 0;
        __syncthreads();
        part[t] += v;
        __syncthreads();
    }
    int run = (t == 0) ? 0 : part[t - 1];
    for (int i = 0; i < CHUNK; i++) {
        int idx = base + i;
        if (idx < NN) {
            g_rowptr[idx] = run;
            g_wp[idx] = run;
            run += g_deg[idx];
        }
    }
    if (t == 1023) g_rowptr[NN] = part[1023];
}

__global__ void scatter_kernel(const int* __restrict__ ei) {
    int e = blockIdx.x * blockDim.x + threadIdx.x;
    if (e >= NE) return;
    int d = ei[NE + e];
    int p = atomicAdd(&g_wp[d], 1);
    g_eids[p] = e;
}

__global__ void zero_stats_kernel() {
    int i = blockIdx.x * blockDim.x + threadIdx.x;
    if (i < 2 * HD) g_bnstat[i] = 0.f;
    if (i < 2 * GG) g_gstat[i] = 0.f;
}

// ---------------- generic fp32 GEMM: C[N,M] = op_A(A[N,K]) @ W[K,M] (+bias)(+add) ----------------
// tS/tT non-null => A elements transformed: a = relu(a*tS[k] + tT[k])  (BN+ReLU on the fly)
// BM=128, BN=64, BK=16, 256 threads, 8x4 per-thread tile.
__global__ __launch_bounds__(256)
void gemm_kernel(const float* __restrict__ A, const float* __restrict__ W,
                 const float* __restrict__ bias, const float* __restrict__ add,
                 const float* __restrict__ tS, const float* __restrict__ tT,
                 float* __restrict__ C, int N, int K, int M) {
    constexpr int BM = 128, BN = 64, BK = 16;
    __shared__ float As[BK][BM];
    __shared__ float Ws[BK][BN];

    int tid = threadIdx.x;
    int ty = tid >> 4, tx = tid & 15;
    int rowBase = blockIdx.x * BM;
    int colBase = blockIdx.y * BN;

    float acc[8][4];
#pragma unroll
    for (int i = 0; i < 8; i++)
#pragma unroll
        for (int j = 0; j < 4; j++) acc[i][j] = 0.f;

    for (int k0 = 0; k0 < K; k0 += BK) {
        // load A tile (transposed into As[k][row])
#pragma unroll
        for (int q = 0; q < 2; q++) {
            int f  = tid * 2 + q;
            int r  = f >> 2;
            int qq = f & 3;
            int grow = rowBase + r;
            int gk   = k0 + qq * 4;
            float4 v = make_float4(0.f, 0.f, 0.f, 0.f);
            if (grow < N) {
                v = *(const float4*)&A[(size_t)grow * K + gk];
                if (tS) {
                    float4 sv = *(const float4*)&tS[gk];
                    float4 tv = *(const float4*)&tT[gk];
                    v.x = fmaxf(fmaf(v.x, sv.x, tv.x), 0.f);
                    v.y = fmaxf(fmaf(v.y, sv.y, tv.y), 0.f);
                    v.z = fmaxf(fmaf(v.z, sv.z, tv.z), 0.f);
                    v.w = fmaxf(fmaf(v.w, sv.w, tv.w), 0.f);
                }
            }
            As[qq * 4 + 0][r] = v.x;
            As[qq * 4 + 1][r] = v.y;
            As[qq * 4 + 2][r] = v.z;
            As[qq * 4 + 3][r] = v.w;
        }
        // load W tile
        {
            int k = tid >> 4;
            int c = (tid & 15) * 4;
            float4 wv = *(const float4*)&W[(size_t)(k0 + k) * M + colBase + c];
            *(float4*)&Ws[k][c] = wv;
        }
        __syncthreads();

#pragma unroll
        for (int kk = 0; kk < BK; kk++) {
            float4 a0 = *(float4*)&As[kk][ty * 8];
            float4 a1 = *(float4*)&As[kk][ty * 8 + 4];
            float4 w  = *(float4*)&Ws[kk][tx * 4];
            float av[8] = {a0.x, a0.y, a0.z, a0.w, a1.x, a1.y, a1.z, a1.w};
            float wv[4] = {w.x, w.y, w.z, w.w};
#pragma unroll
            for (int i = 0; i < 8; i++)
#pragma unroll
                for (int j = 0; j < 4; j++)
                    acc[i][j] = fmaf(av[i], wv[j], acc[i][j]);
        }
        __syncthreads();
    }

    int colb = colBase + tx * 4;
    float4 bv = make_float4(0.f, 0.f, 0.f, 0.f);
    if (bias) bv = *(const float4*)&bias[colb];
#pragma unroll
    for (int i = 0; i < 8; i++) {
        int grow = rowBase + ty * 8 + i;
        if (grow >= N) break;
        float4 o = make_float4(acc[i][0] + bv.x, acc[i][1] + bv.y,
                               acc[i][2] + bv.z, acc[i][3] + bv.w);
        if (add) {
            float4 av = *(const float4*)&add[(size_t)grow * M + colb];
            o.x += av.x; o.y += av.y; o.z += av.z; o.w += av.w;
        }
        *(float4*)&C[(size_t)grow * M + colb] = o;
    }
}

// ---------------- edge alpha: alpha[e,h] = sum_c leaky(xl[src]+xr[dst]+e)[h,c]*att[h,c] ----------------
__device__ __forceinline__ float lky(float v) { return v > 0.f ? v : NEG * v; }

__global__ __launch_bounds__(256)
void edge_alpha_kernel(const int* __restrict__ ei, const float* __restrict__ att) {
    __shared__ float att_s[DD];
    if (threadIdx.x < DD) att_s[threadIdx.x] = att[threadIdx.x];
    __syncthreads();
    int lane = threadIdx.x & 31;
    int warp = (blockIdx.x * blockDim.x + threadIdx.x) >> 5;
    int nw   = (gridDim.x * blockDim.x) >> 5;
    float4 attv = *(float4*)&att_s[lane * 4];
    for (int e = warp; e < NE; e += nw) {
        int s = ei[e];
        int d = ei[NE + e];
        float4 xlv = *(const float4*)&g_xl[(size_t)s * DD + lane * 4];
        float4 xrv = *(const float4*)&g_xr[(size_t)d * DD + lane * 4];
        float4 ev  = *(const float4*)&g_e [(size_t)e * DD + lane * 4];
        float mx = lky(xlv.x + xrv.x + ev.x);
        float my = lky(xlv.y + xrv.y + ev.y);
        float mz = lky(xlv.z + xrv.z + ev.z);
        float mw = lky(xlv.w + xrv.w + ev.w);
        float p = mx * attv.x + my * attv.y + mz * attv.z + mw * attv.w;
        p += __shfl_xor_sync(0xffffffffu, p, 1);
        p += __shfl_xor_sync(0xffffffffu, p, 2);
        if ((lane & 3) == 0) g_alpha[(size_t)e * NH + (lane >> 2)] = p;
    }
}

// ---------------- node aggregation: online softmax over incoming edges ----------------
__global__ __launch_bounds__(256)
void node_agg_kernel(const int* __restrict__ ei) {
    int lane = threadIdx.x & 31;
    int n = blockIdx.x * 8 + (threadIdx.x >> 5);
    if (n >= NN) return;
    int h = lane >> 2;
    int beg = g_rowptr[n], end = g_rowptr[n + 1];
    float m = NEG_INF, den = 0.f;
    float4 acc = make_float4(0.f, 0.f, 0.f, 0.f);
    for (int j = beg; j < end; j++) {
        int e = g_eids[j];
        float a = g_alpha[(size_t)e * NH + h];
        int s = ei[e];
        float4 xlv = *(const float4*)&g_xl[(size_t)s * DD + lane * 4];
        float mn = fmaxf(m, a);
        float corr = __expf(m - mn);
        float p = __expf(a - mn);
        den = den * corr + p;
        acc.x = acc.x * corr + p * xlv.x;
        acc.y = acc.y * corr + p * xlv.y;
        acc.z = acc.z * corr + p * xlv.z;
        acc.w = acc.w * corr + p * xlv.w;
        m = mn;
    }
    float inv = 1.f / (den + 1e-16f);
    float4 rv = *(const float4*)&g_xres[(size_t)n * DD + lane * 4];
    float4 o = make_float4(acc.x * inv + rv.x, acc.y * inv + rv.y,
                           acc.z * inv + rv.z, acc.w * inv + rv.w);
    *(float4*)&g_xtmp[(size_t)n * DD + lane * 4] = o;
}

// ---------------- BN column stats over g_h [NN, HD] ----------------
__global__ void colstats_kernel() {
    int col = blockIdx.x * 128 + threadIdx.x;
    constexpr int CHUNK = (NN + 63) / 64;  // 782
    int r0 = blockIdx.y * CHUNK;
    int r1 = min(r0 + CHUNK, NN);
    float s = 0.f, q = 0.f;
    for (int r = r0; r < r1; r++) {
        float v = g_h[(size_t)r * HD + col];
        s += v;
        q += v * v;
    }
    atomicAdd(&g_bnstat[col], s);
    atomicAdd(&g_bnstat[HD + col], q);
}

__global__ void bn_final_kernel(const float* __restrict__ gamma, const float* __restrict__ beta) {
    int c = threadIdx.x;
    if (c >= HD) return;
    float invn = 1.f / (float)NN;
    float mu  = g_bnstat[c] * invn;
    float var = g_bnstat[HD + c] * invn - mu * mu;
    float istd = rsqrtf(var + EPSC);
    float s = gamma[c] * istd;
    g_bns[c] = s;
    g_bnt[c] = beta[c] - mu * s;
}

// ---------------- graph LayerNorm stats over g_x2 ----------------
__global__ __launch_bounds__(256)
void ln_stats_kernel(const int* __restrict__ nb) {
    int lane = threadIdx.x & 31;
    int n = blockIdx.x * 8 + (threadIdx.x >> 5);
    if (n >= NN) return;
    float4 v = *(const float4*)&g_x2[(size_t)n * DD + lane * 4];
    float s = v.x + v.y + v.z + v.w;
    float q = v.x * v.x + v.y * v.y + v.z * v.z + v.w * v.w;
#pragma unroll
    for (int off = 16; off > 0; off >>= 1) {
        s += __shfl_xor_sync(0xffffffffu, s, off);
        q += __shfl_xor_sync(0xffffffffu, q, off);
    }
    if (lane == 0) {
        int g = nb[n];
        atomicAdd(&g_gstat[g], s);
        atomicAdd(&g_gstat[GG + g], q);
    }
}

__global__ void ln_final_kernel() {
    int g = threadIdx.x;
    if (g >= GG) return;
    float cnt = fmaxf((float)g_gcnt[g], 1.f);
    float denom = cnt * (float)DD;
    float mean = g_gstat[g] / denom;
    float var  = g_gstat[GG + g] / denom - mean * mean;
    g_gmean[g] = mean;
    g_ginv[g]  = rsqrtf(var + EPSC);
}

__global__ void ln_apply_kernel(const int* __restrict__ nb,
                                const float* __restrict__ gamma,
                                const float* __restrict__ beta,
                                float* __restrict__ dst) {
    int idx = blockIdx.x * blockDim.x + threadIdx.x;  // float4 granularity
    if (idx >= NN * (DD / 4)) return;
    int n  = idx >> 5;
    int c4 = (idx & 31) * 4;
    int g  = nb[n];
    float mean = g_gmean[g];
    float ginv = g_ginv[g];
    float4 v  = *(const float4*)&g_x2[(size_t)n * DD + c4];
    float4 ga = *(const float4*)&gamma[c4];
    float4 be = *(const float4*)&beta[c4];
    float4 o;
    o.x = (v.x - mean) * ginv * ga.x + be.x;
    o.y = (v.y - mean) * ginv * ga.y + be.y;
    o.z = (v.z - mean) * ginv * ga.z + be.z;
    o.w = (v.w - mean) * ginv * ga.w + be.w;
    *(float4*)&dst[(size_t)n * DD + c4] = o;
}

// ---------------- host launch ----------------
extern "C" void kernel_launch(void* const* d_in, const int* in_sizes, int n_in,
                              void* d_out, int out_size) {
    const float* x    = (const float*)d_in[0];
    const int*   nb   = (const int*)  d_in[1];
    const int*   ei   = (const int*)  d_in[2];
    const float* ea   = (const float*)d_in[3];
    const float* Wl   = (const float*)d_in[4];
    const float* bl   = (const float*)d_in[5];
    const float* Wr   = (const float*)d_in[6];
    const float* br   = (const float*)d_in[7];
    const float* We   = (const float*)d_in[8];
    const float* att  = (const float*)d_in[9];
    const float* bias = (const float*)d_in[10];
    const float* Wres = (const float*)d_in[11];
    const float* W1   = (const float*)d_in[12];
    const float* b1   = (const float*)d_in[13];
    const float* bng  = (const float*)d_in[14];
    const float* bnb  = (const float*)d_in[15];
    const float* W2   = (const float*)d_in[16];
    const float* b2   = (const float*)d_in[17];
    const float* lng  = (const float*)d_in[18];
    const float* lnb  = (const float*)d_in[19];
    float* out = (float*)d_out;

    void* p;
    cudaGetSymbolAddress(&p, g_xl);   float* pxl   = (float*)p;
    cudaGetSymbolAddress(&p, g_xr);   float* pxr   = (float*)p;
    cudaGetSymbolAddress(&p, g_xres); float* pxres = (float*)p;
    cudaGetSymbolAddress(&p, g_xtmp); float* pxtmp = (float*)p;
    cudaGetSymbolAddress(&p, g_x2);   float* px2   = (float*)p;
    cudaGetSymbolAddress(&p, g_xcur); float* pxcur = (float*)p;
    cudaGetSymbolAddress(&p, g_e);    float* pe    = (float*)p;
    cudaGetSymbolAddress(&p, g_h);    float* ph    = (float*)p;
    cudaGetSymbolAddress(&p, g_bns);  float* pbns  = (float*)p;
    cudaGetSymbolAddress(&p, g_bnt);  float* pbnt  = (float*)p;

    // CSR build + graph counts (shared by both layers)
    zero_init_kernel<<<(NN + 255) / 256, 256>>>();
    hist_kernel<<<(NE + 255) / 256, 256>>>(ei, nb);
    scan_kernel<<<1, 1024>>>();
    scatter_kernel<<<(NE + 255) / 256, 256>>>(ei);

    const int GR = (NN + 127) / 128;   // 391
    const int GE = (NE + 127) / 128;   // 6250

    const float* xin = x;
    for (int l = 0; l < 2; l++) {
        zero_stats_kernel<<<2, 1024>>>();

        gemm_kernel<<<dim3(GR, 2), 256>>>(xin, Wl + (size_t)l * DD * DD, bl + l * DD,
                                          nullptr, nullptr, nullptr, pxl, NN, DD, DD);
        gemm_kernel<<<dim3(GR, 2), 256>>>(xin, Wr + (size_t)l * DD * DD, br + l * DD,
                                          nullptr, nullptr, nullptr, pxr, NN, DD, DD);
        gemm_kernel<<<dim3(GR, 2), 256>>>(xin, Wres + (size_t)l * DD * DD, bias + l * DD,
                                          nullptr, nullptr, nullptr, pxres, NN, DD, DD);
        gemm_kernel<<<dim3(GE, 2), 256>>>(ea, We + (size_t)l * EDD * DD, nullptr,
                                          nullptr, nullptr, nullptr, pe, NE, EDD, DD);

        edge_alpha_kernel<<<1184, 256>>>(ei, att + l * DD);
        node_agg_kernel<<<(NN + 7) / 8, 256>>>(ei);

        gemm_kernel<<<dim3(GR, 8), 256>>>(pxtmp, W1 + (size_t)l * DD * HD, b1 + l * HD,
                                          nullptr, nullptr, nullptr, ph, NN, DD, HD);
        colstats_kernel<<<dim3(4, 64), 128>>>();
        bn_final_kernel<<<1, 512>>>(bng + l * HD, bnb + l * HD);
        gemm_kernel<<<dim3(GR, 2), 256>>>(ph, W2 + (size_t)l * HD * DD, b2 + l * DD,
                                          pxtmp, pbns, pbnt, px2, NN, HD, DD);

        ln_stats_kernel<<<(NN + 7) / 8, 256>>>(nb);
        ln_final_kernel<<<1, 64>>>();
        float* dst = (l == 1) ? out : pxcur;
        ln_apply_kernel<<<(NN * (DD / 4) + 255) / 256, 256>>>(nb, lng + l * DD, lnb + l * DD, dst);

        xin = pxcur;
    }
}